// round 1
// baseline (speedup 1.0000x reference)
#include <cuda_runtime.h>

#define N_RAYS   65536
#define N_SAMPLES 128

// One warp per ray. Lane l owns samples [4l, 4l+4).
// weight_i = max(0, sig_i - sig_{i+1}) / sig_0  (telescoped cumprod),
// weight_0 = weight_{S-1} = 0.
__global__ __launch_bounds__(256) void neus_render_kernel(
    const float* __restrict__ sdf,      // [R, S]
    const float* __restrict__ color,    // [R, S, 3]
    const float* __restrict__ z_vals,   // [R, S]
    const float* __restrict__ s_ptr,    // [1]
    const float* __restrict__ bg,       // [3]
    float* __restrict__ out)            // [R*3 pixel | R invdepth | R*S weight]
{
    const unsigned FULL = 0xffffffffu;
    int warp_global = (blockIdx.x * blockDim.x + threadIdx.x) >> 5;
    int lane = threadIdx.x & 31;
    if (warp_global >= N_RAYS) return;
    const int ray = warp_global;

    const float s = s_ptr[0];

    // ---- sdf -> sigmoid (4 samples per lane, float4 coalesced) ----
    const float4 sd = reinterpret_cast<const float4*>(sdf + (size_t)ray * N_SAMPLES)[lane];
    float sg0 = 1.0f / (1.0f + __expf(-sd.x * s));
    float sg1 = 1.0f / (1.0f + __expf(-sd.y * s));
    float sg2 = 1.0f / (1.0f + __expf(-sd.z * s));
    float sg3 = 1.0f / (1.0f + __expf(-sd.w * s));

    // neighbor lane's first sigmoid = sigmoid of sample 4l+4
    float sg_next = __shfl_down_sync(FULL, sg0, 1);
    // sigmoid of sample 0 of this ray (lane 0's sg0)
    float sig_first = __shfl_sync(FULL, sg0, 0);
    float inv_sig0 = 1.0f / sig_first;

    // ---- weights ----
    float w0 = (lane == 0)  ? 0.0f : fmaxf(0.0f, sg0 - sg1) * inv_sig0;
    float w1 =                       fmaxf(0.0f, sg1 - sg2) * inv_sig0;
    float w2 =                       fmaxf(0.0f, sg2 - sg3) * inv_sig0;
    float w3 = (lane == 31) ? 0.0f : fmaxf(0.0f, sg3 - sg_next) * inv_sig0;

    // ---- inverse depth ----
    const float4 zz = reinterpret_cast<const float4*>(z_vals + (size_t)ray * N_SAMPLES)[lane];
    float invd = w0 / zz.x + w1 / zz.y + w2 / zz.z + w3 / zz.w;

    // ---- color accumulation (12 contiguous floats = 3 float4) ----
    const float4* c4 = reinterpret_cast<const float4*>(
        color + ((size_t)ray * N_SAMPLES + lane * 4) * 3);
    float4 c0 = c4[0];  // s0.r s0.g s0.b s1.r
    float4 c1 = c4[1];  // s1.g s1.b s2.r s2.g
    float4 c2 = c4[2];  // s2.b s3.r s3.g s3.b

    float pr = w0 * c0.x + w1 * c0.w + w2 * c1.z + w3 * c2.y;
    float pg = w0 * c0.y + w1 * c1.x + w2 * c1.w + w3 * c2.z;
    float pb = w0 * c0.z + w1 * c1.y + w2 * c2.x + w3 * c2.w;
    float wsum = w0 + w1 + w2 + w3;

    // ---- write weights (coalesced float4 per lane) ----
    float* out_weight = out + (size_t)N_RAYS * 4;  // after pixel (3R) + invdepth (R)
    reinterpret_cast<float4*>(out_weight + (size_t)ray * N_SAMPLES)[lane] =
        make_float4(w0, w1, w2, w3);

    // ---- warp reductions (5 values) ----
    #pragma unroll
    for (int off = 16; off > 0; off >>= 1) {
        pr   += __shfl_down_sync(FULL, pr,   off);
        pg   += __shfl_down_sync(FULL, pg,   off);
        pb   += __shfl_down_sync(FULL, pb,   off);
        wsum += __shfl_down_sync(FULL, wsum, off);
        invd += __shfl_down_sync(FULL, invd, off);
    }

    if (lane == 0) {
        float resid = 1.0f - wsum;
        float* out_pixel    = out;
        float* out_invdepth = out + (size_t)N_RAYS * 3;
        out_pixel[ray * 3 + 0] = pr + resid * bg[0];
        out_pixel[ray * 3 + 1] = pg + resid * bg[1];
        out_pixel[ray * 3 + 2] = pb + resid * bg[2];
        out_invdepth[ray] = invd;
    }
}

extern "C" void kernel_launch(void* const* d_in, const int* in_sizes, int n_in,
                              void* d_out, int out_size) {
    const float* sdf    = (const float*)d_in[0];
    const float* color  = (const float*)d_in[1];
    const float* z_vals = (const float*)d_in[2];
    const float* s      = (const float*)d_in[3];
    const float* bg     = (const float*)d_in[4];
    float* out = (float*)d_out;

    // 1 warp per ray, 8 warps per block
    const int threads = 256;
    const int warps_per_block = threads / 32;
    const int blocks = (N_RAYS + warps_per_block - 1) / warps_per_block;
    neus_render_kernel<<<blocks, threads>>>(sdf, color, z_vals, s, bg, out);
}

// round 3
// speedup vs baseline: 1.1757x; 1.1757x over previous
#include <cuda_runtime.h>

#define N_RAYS   65536
#define N_SAMPLES 128

// One warp per ray. Lane l owns samples [4l, 4l+4).
// weight_i = max(0, sig_i - sig_{i+1}) / sig_0  (telescoped cumprod),
// weight_0 = weight_{S-1} = 0.
// All divisions via MUFU.RCP fast paths (rel err ~2^-22, tolerance 1e-3).
__global__ __launch_bounds__(256) void neus_render_kernel(
    const float* __restrict__ sdf,      // [R, S]
    const float* __restrict__ color,    // [R, S, 3]
    const float* __restrict__ z_vals,   // [R, S]
    const float* __restrict__ s_ptr,    // [1]
    const float* __restrict__ bg,       // [3]
    float* __restrict__ out)            // [R*3 pixel | R invdepth | R*S weight]
{
    const unsigned FULL = 0xffffffffu;
    int warp_global = (blockIdx.x * blockDim.x + threadIdx.x) >> 5;
    int lane = threadIdx.x & 31;
    if (warp_global >= N_RAYS) return;
    const int ray = warp_global;

    const float s = s_ptr[0];

    // ---- issue all streaming loads up front (max MLP) ----
    const float4 sd = __ldcs(reinterpret_cast<const float4*>(sdf + (size_t)ray * N_SAMPLES) + lane);
    const float4 zz = __ldcs(reinterpret_cast<const float4*>(z_vals + (size_t)ray * N_SAMPLES) + lane);
    const float4* c4 = reinterpret_cast<const float4*>(
        color + ((size_t)ray * N_SAMPLES + lane * 4) * 3);
    float4 c0 = __ldcs(c4 + 0);  // s0.r s0.g s0.b s1.r
    float4 c1 = __ldcs(c4 + 1);  // s1.g s1.b s2.r s2.g
    float4 c2 = __ldcs(c4 + 2);  // s2.b s3.r s3.g s3.b

    // ---- sdf -> sigmoid (fast rcp) ----
    float sg0 = __fdividef(1.0f, 1.0f + __expf(-sd.x * s));
    float sg1 = __fdividef(1.0f, 1.0f + __expf(-sd.y * s));
    float sg2 = __fdividef(1.0f, 1.0f + __expf(-sd.z * s));
    float sg3 = __fdividef(1.0f, 1.0f + __expf(-sd.w * s));

    // neighbor lane's first sigmoid = sigmoid of sample 4l+4
    float sg_next = __shfl_down_sync(FULL, sg0, 1);
    // sigmoid of sample 0 of this ray (lane 0's sg0)
    float sig_first = __shfl_sync(FULL, sg0, 0);
    float inv_sig0 = __fdividef(1.0f, sig_first);

    // ---- weights ----
    float w0 = (lane == 0)  ? 0.0f : fmaxf(0.0f, sg0 - sg1) * inv_sig0;
    float w1 =                       fmaxf(0.0f, sg1 - sg2) * inv_sig0;
    float w2 =                       fmaxf(0.0f, sg2 - sg3) * inv_sig0;
    float w3 = (lane == 31) ? 0.0f : fmaxf(0.0f, sg3 - sg_next) * inv_sig0;

    // ---- inverse depth (fast division) ----
    float invd = __fdividef(w0, zz.x) + __fdividef(w1, zz.y)
               + __fdividef(w2, zz.z) + __fdividef(w3, zz.w);

    // ---- color accumulation ----
    float pr = w0 * c0.x + w1 * c0.w + w2 * c1.z + w3 * c2.y;
    float pg = w0 * c0.y + w1 * c1.x + w2 * c1.w + w3 * c2.z;
    float pb = w0 * c0.z + w1 * c1.y + w2 * c2.x + w3 * c2.w;
    float wsum = w0 + w1 + w2 + w3;

    // ---- write weights (coalesced float4, streaming) ----
    float* out_weight = out + (size_t)N_RAYS * 4;  // after pixel (3R) + invdepth (R)
    __stcs(reinterpret_cast<float4*>(out_weight + (size_t)ray * N_SAMPLES) + lane,
           make_float4(w0, w1, w2, w3));

    // ---- warp reductions (5 values) ----
    #pragma unroll
    for (int off = 16; off > 0; off >>= 1) {
        pr   += __shfl_down_sync(FULL, pr,   off);
        pg   += __shfl_down_sync(FULL, pg,   off);
        pb   += __shfl_down_sync(FULL, pb,   off);
        wsum += __shfl_down_sync(FULL, wsum, off);
        invd += __shfl_down_sync(FULL, invd, off);
    }

    if (lane == 0) {
        float resid = 1.0f - wsum;
        float* out_pixel    = out;
        float* out_invdepth = out + (size_t)N_RAYS * 3;
        out_pixel[ray * 3 + 0] = pr + resid * bg[0];
        out_pixel[ray * 3 + 1] = pg + resid * bg[1];
        out_pixel[ray * 3 + 2] = pb + resid * bg[2];
        out_invdepth[ray] = invd;
    }
}

extern "C" void kernel_launch(void* const* d_in, const int* in_sizes, int n_in,
                              void* d_out, int out_size) {
    const float* sdf    = (const float*)d_in[0];
    const float* color  = (const float*)d_in[1];
    const float* z_vals = (const float*)d_in[2];
    const float* s      = (const float*)d_in[3];
    const float* bg     = (const float*)d_in[4];
    float* out = (float*)d_out;

    const int threads = 256;
    const int warps_per_block = threads / 32;
    const int blocks = (N_RAYS + warps_per_block - 1) / warps_per_block;
    neus_render_kernel<<<blocks, threads>>>(sdf, color, z_vals, s, bg, out);
}